// round 7
// baseline (speedup 1.0000x reference)
#include <cuda_runtime.h>

#define NMAX 100000
#define NEMAX 1700000

// Scratch (__device__ globals; allocation-free rule)
__device__ __align__(16) float g_Y1[NMAX * 32];
__device__ __align__(16) float g_Y2[NMAX * 32];
__device__ float g_S[NMAX];
__device__ int   g_cnt[NMAX];
__device__ int   g_off[NMAX + 1];
__device__ int   g_cur[NMAX];
__device__ int   g_ssrc[NEMAX];
__device__ int   g_is64;            // 1 if edge_index is int64, 0 if int32
// Folded weights:
__device__ float g_W12[32 * 32];    // w1b @ w2a
__device__ float g_b12[32];         // b1b @ w2a
__device__ float g_w23[32];         // w2b @ w3
__device__ float g_c23;             // b2b . w3

// ---------------------------------------------------------------------------
// K0: dtype detect (int64 odd words are zero high halves) + weight folding.
// ---------------------------------------------------------------------------
__global__ void k_init(const int* __restrict__ ei_w, int nWords,
                       const float* __restrict__ w1b, const float* __restrict__ b1b,
                       const float* __restrict__ w2a, const float* __restrict__ w2b,
                       const float* __restrict__ b2b, const float* __restrict__ w3) {
    __shared__ int any_nonzero;
    int tid = threadIdx.x;
    if (tid == 0) any_nonzero = 0;
    __syncthreads();
    int nz = 0;
    for (int i = tid; i < 2048; i += blockDim.x) {
        int w = 2 * i + 1;
        if (w < nWords && ei_w[w] != 0) nz = 1;
    }
    if (nz) atomicOr(&any_nonzero, 1);
    __syncthreads();
    if (tid == 0) g_is64 = any_nonzero ? 0 : 1;

    int k = tid >> 5, o = tid & 31;
    float acc = 0.f;
#pragma unroll
    for (int j = 0; j < 32; ++j)
        acc = fmaf(w1b[k * 32 + j], w2a[j * 32 + o], acc);
    g_W12[k * 32 + o] = acc;

    if (tid < 32) {
        float b = 0.f, w = 0.f;
#pragma unroll
        for (int j = 0; j < 32; ++j) {
            b = fmaf(b1b[j], w2a[j * 32 + tid], b);
            w = fmaf(w2b[tid * 32 + j], w3[j], w);
        }
        g_b12[tid] = b;
        g_w23[tid] = w;
    }
    if (tid == 0) {
        float c = 0.f;
#pragma unroll
        for (int j = 0; j < 32; ++j) c = fmaf(b2b[j], w3[j], c);
        g_c23 = c;
    }
}

__device__ __forceinline__ void load_edge(const int* __restrict__ ei, int nE,
                                          int e, int& src, int& dst) {
    if (g_is64) {
        const long long* p = (const long long*)ei;
        src = (int)p[e];
        dst = (int)p[(size_t)nE + e];
    } else {
        src = ei[e];
        dst = ei[nE + e];
    }
}

// --------------------------- CSR build (counting sort by dst) ---------------
__global__ void k_zero(int nN) {
    int i = blockIdx.x * blockDim.x + threadIdx.x;
    if (i < nN) g_cnt[i] = 0;
}

__global__ void k_count(const int* __restrict__ ei, int nE) {
    int e = blockIdx.x * blockDim.x + threadIdx.x;
    if (e >= nE) return;
    int src, dst;
    load_edge(ei, nE, e, src, dst);
    atomicAdd(&g_cnt[dst], 1);
}

// Single-block exclusive scan over g_cnt -> g_off (+ copy g_cur), g_off[nN]=nE.
__global__ void k_scan(int nN, int nE) {
    __shared__ int sm[2][1024];
    int tid = threadIdx.x;
    int chunk = (nN + 1023) >> 10;
    int beg = tid * chunk;
    int end = min(beg + chunk, nN);
    int sum = 0;
    for (int i = beg; i < end; ++i) sum += g_cnt[i];
    sm[0][tid] = sum;
    __syncthreads();
    int p = 0;
#pragma unroll
    for (int off = 1; off < 1024; off <<= 1) {
        int v = sm[p][tid] + ((tid >= off) ? sm[p][tid - off] : 0);
        sm[p ^ 1][tid] = v;
        __syncthreads();
        p ^= 1;
    }
    int run = sm[p][tid] - sum;   // exclusive base
    for (int i = beg; i < end; ++i) {
        g_off[i] = run;
        g_cur[i] = run;
        run += g_cnt[i];
    }
    if (tid == 0) g_off[nN] = nE;
}

__global__ void k_scatter(const int* __restrict__ ei, int nE) {
    int e = blockIdx.x * blockDim.x + threadIdx.x;
    if (e >= nE) return;
    int src, dst;
    load_edge(ei, nE, e, src, dst);
    int pos = atomicAdd(&g_cur[dst], 1);
    g_ssrc[pos] = src;
}

// ---------------------------------------------------------------------------
// K1: y1 = x @ w1a  (nN x 128)@(128 x 32). 4 warps, 2 adjacent nodes per iter,
// weight slice in regs, 4-way split accumulators, one barrier per iteration.
// Writes only Y1 (aggregation no longer needs a Z prestore).
// ---------------------------------------------------------------------------
__global__ __launch_bounds__(128, 8) void k_proj1(const float* __restrict__ x,
                        const float* __restrict__ w1a, int nN) {
    const int lane = threadIdx.x & 31;
    const int wid  = threadIdx.x >> 5;   // 0..3
    float wreg[32];
#pragma unroll
    for (int k = 0; k < 32; ++k)
        wreg[k] = w1a[(wid * 32 + k) * 32 + lane];

    __shared__ float part[2][2][4][32];  // [buf][node][warp][lane]

    int buf = 0;
    for (int base = blockIdx.x * 2; base < nN; base += gridDim.x * 2) {
        int n1 = base + 1;
        bool has1 = (n1 < nN);
        float xa = x[(size_t)base * 128 + wid * 32 + lane];
        float xb = has1 ? x[(size_t)n1 * 128 + wid * 32 + lane] : 0.f;
        float a0 = 0.f, a1 = 0.f, a2 = 0.f, a3 = 0.f;
        float c0 = 0.f, c1 = 0.f, c2 = 0.f, c3 = 0.f;
#pragma unroll
        for (int k = 0; k < 32; k += 4) {
            a0 = fmaf(__shfl_sync(0xffffffffu, xa, k + 0), wreg[k + 0], a0);
            c0 = fmaf(__shfl_sync(0xffffffffu, xb, k + 0), wreg[k + 0], c0);
            a1 = fmaf(__shfl_sync(0xffffffffu, xa, k + 1), wreg[k + 1], a1);
            c1 = fmaf(__shfl_sync(0xffffffffu, xb, k + 1), wreg[k + 1], c1);
            a2 = fmaf(__shfl_sync(0xffffffffu, xa, k + 2), wreg[k + 2], a2);
            c2 = fmaf(__shfl_sync(0xffffffffu, xb, k + 2), wreg[k + 2], c2);
            a3 = fmaf(__shfl_sync(0xffffffffu, xa, k + 3), wreg[k + 3], a3);
            c3 = fmaf(__shfl_sync(0xffffffffu, xb, k + 3), wreg[k + 3], c3);
        }
        part[buf][0][wid][lane] = (a0 + a1) + (a2 + a3);
        part[buf][1][wid][lane] = (c0 + c1) + (c2 + c3);
        __syncthreads();
        if (wid == 0) {
            g_Y1[base * 32 + lane] = part[buf][0][0][lane] + part[buf][0][1][lane]
                                   + part[buf][0][2][lane] + part[buf][0][3][lane];
        } else if (wid == 1 && has1) {
            g_Y1[n1 * 32 + lane] = part[buf][1][0][lane] + part[buf][1][1][lane]
                                 + part[buf][1][2][lane] + part[buf][1][3][lane];
        }
        buf ^= 1;
    }
}

// ---------------------------------------------------------------------------
// K2: fused aggregation + MLP1 (+ conv2 first linear, folded into W12).
// Warp per dst node: lanes = channels. z1 = Y1[dst] + sum Y1[src in-edges]
// (register accumulation, no atomics), then y2 = relu(z1+b1a)@W12 + b12.
// ---------------------------------------------------------------------------
__global__ __launch_bounds__(256, 4) void k_aggmlp1(const float* __restrict__ b1a, int nN) {
    const int lane = threadIdx.x & 31;
    float wc[32];
#pragma unroll
    for (int k = 0; k < 32; ++k)
        wc[k] = g_W12[k * 32 + lane];
    const float ba = b1a[lane];
    const float bb = g_b12[lane];

    int gw = (blockIdx.x * blockDim.x + threadIdx.x) >> 5;
    int nw = (gridDim.x * blockDim.x) >> 5;
    for (int dst = gw; dst < nN; dst += nw) {
        int beg = g_off[dst], end = g_off[dst + 1];
        float a0 = g_Y1[dst * 32 + lane];   // self (eps = 0)
        float a1 = 0.f, a2 = 0.f, a3 = 0.f;
        int i = beg;
        for (; i + 4 <= end; i += 4) {
            int s0 = g_ssrc[i], s1 = g_ssrc[i + 1], s2 = g_ssrc[i + 2], s3 = g_ssrc[i + 3];
            a0 += g_Y1[s0 * 32 + lane];
            a1 += g_Y1[s1 * 32 + lane];
            a2 += g_Y1[s2 * 32 + lane];
            a3 += g_Y1[s3 * 32 + lane];
        }
        for (; i < end; ++i) a0 += g_Y1[g_ssrc[i] * 32 + lane];
        float z = (a0 + a1) + (a2 + a3);
        float t = fmaxf(z + ba, 0.f);
        float y0 = bb, y1 = 0.f, y2 = 0.f, y3 = 0.f;
#pragma unroll
        for (int k = 0; k < 32; k += 4) {
            y0 = fmaf(__shfl_sync(0xffffffffu, t, k + 0), wc[k + 0], y0);
            y1 = fmaf(__shfl_sync(0xffffffffu, t, k + 1), wc[k + 1], y1);
            y2 = fmaf(__shfl_sync(0xffffffffu, t, k + 2), wc[k + 2], y2);
            y3 = fmaf(__shfl_sync(0xffffffffu, t, k + 3), wc[k + 3], y3);
        }
        g_Y2[dst * 32 + lane] = (y0 + y1) + (y2 + y3);
    }
}

// ---------------------------------------------------------------------------
// K3: fused aggregation + MLP2 (+ conv3 linear, folded into w23).
// z2 = Y2[dst] + sum Y2[src]; S[dst] = sum_lane relu(z2+b2a)*w23 + c23.
// ---------------------------------------------------------------------------
__global__ __launch_bounds__(256, 8) void k_aggs(const float* __restrict__ b2a, int nN) {
    const int lane = threadIdx.x & 31;
    const float ba = b2a[lane];
    const float wl = g_w23[lane];
    const float c23 = g_c23;

    int gw = (blockIdx.x * blockDim.x + threadIdx.x) >> 5;
    int nw = (gridDim.x * blockDim.x) >> 5;
    for (int dst = gw; dst < nN; dst += nw) {
        int beg = g_off[dst], end = g_off[dst + 1];
        float a0 = g_Y2[dst * 32 + lane];
        float a1 = 0.f, a2 = 0.f, a3 = 0.f;
        int i = beg;
        for (; i + 4 <= end; i += 4) {
            int s0 = g_ssrc[i], s1 = g_ssrc[i + 1], s2 = g_ssrc[i + 2], s3 = g_ssrc[i + 3];
            a0 += g_Y2[s0 * 32 + lane];
            a1 += g_Y2[s1 * 32 + lane];
            a2 += g_Y2[s2 * 32 + lane];
            a3 += g_Y2[s3 * 32 + lane];
        }
        for (; i < end; ++i) a0 += g_Y2[g_ssrc[i] * 32 + lane];
        float z = (a0 + a1) + (a2 + a3);
        float sp = fmaxf(z + ba, 0.f) * wl;
#pragma unroll
        for (int o = 16; o > 0; o >>= 1)
            sp += __shfl_xor_sync(0xffffffffu, sp, o);
        if (lane == 0) g_S[dst] = sp + c23;
    }
}

// ---------------------------------------------------------------------------
// K4: conv3 aggregation, thread per dst: out = S[dst] + sum S[src] + b3.
// ---------------------------------------------------------------------------
__global__ void k_out(const float* __restrict__ b3, float* __restrict__ out, int nN) {
    int dst = blockIdx.x * blockDim.x + threadIdx.x;
    if (dst >= nN) return;
    int beg = g_off[dst], end = g_off[dst + 1];
    float a0 = g_S[dst], a1 = 0.f, a2 = 0.f, a3 = 0.f;
    int i = beg;
    for (; i + 4 <= end; i += 4) {
        a0 += g_S[g_ssrc[i]];
        a1 += g_S[g_ssrc[i + 1]];
        a2 += g_S[g_ssrc[i + 2]];
        a3 += g_S[g_ssrc[i + 3]];
    }
    for (; i < end; ++i) a0 += g_S[g_ssrc[i]];
    out[dst] = (a0 + a1) + (a2 + a3) + b3[0];
}

// ---------------------------------------------------------------------------
extern "C" void kernel_launch(void* const* d_in, const int* in_sizes, int n_in,
                              void* d_out, int out_size) {
    const float* x   = (const float*)d_in[0];
    const int*   ei  = (const int*)d_in[1];
    const float* w1a = (const float*)d_in[2];
    const float* b1a = (const float*)d_in[3];
    const float* w1b = (const float*)d_in[4];
    const float* b1b = (const float*)d_in[5];
    const float* w2a = (const float*)d_in[6];
    const float* b2a = (const float*)d_in[7];
    const float* w2b = (const float*)d_in[8];
    const float* b2b = (const float*)d_in[9];
    const float* w3  = (const float*)d_in[10];
    const float* b3  = (const float*)d_in[11];

    int nN = in_sizes[0] / 128;
    int nE = in_sizes[1] / 2;
    float* out = (float*)d_out;

    // dtype detect + weight folding
    k_init<<<1, 1024>>>(ei, 2 * nE, w1b, b1b, w2a, w2b, b2b, w3);
    // CSR build: counting sort by destination
    k_zero<<<(nN + 255) / 256, 256>>>(nN);
    k_count<<<(nE + 255) / 256, 256>>>(ei, nE);
    k_scan<<<1, 1024>>>(nN, nE);
    k_scatter<<<(nE + 255) / 256, 256>>>(ei, nE);
    // conv1 projection 128->32 (commutes with aggregation)
    k_proj1<<<4736, 128>>>(x, w1a, nN);
    // conv1 aggregate + MLP1 (+conv2 lin A) fused, atomic-free
    k_aggmlp1<<<2368, 256>>>(b1a, nN);
    // conv2 aggregate + MLP2 (+conv3 lin) fused -> scalar S
    k_aggs<<<2368, 256>>>(b2a, nN);
    // conv3 aggregate scalars -> out
    k_out<<<(nN + 255) / 256, 256>>>(b3, out, nN);
}

// round 10
// speedup vs baseline: 1.8075x; 1.8075x over previous
#include <cuda_runtime.h>

#define NMAX 100000
#define NEMAX 1700000
#define SCAN_BS 256
#define NBMAX ((NMAX + SCAN_BS - 1) / SCAN_BS)

// Scratch (__device__ globals; allocation-free rule)
__device__ __align__(16) float g_Y1[NMAX * 32];
__device__ __align__(16) float g_Y2[NMAX * 32];
__device__ float g_S[NMAX];
__device__ int   g_cnt[NMAX];
__device__ int   g_off[NMAX + 1];
__device__ int   g_cur[NMAX];
__device__ int   g_ssrc[NEMAX];
__device__ int   g_bsum[NBMAX];
__device__ int   g_is64;            // 1 if edge_index is int64, 0 if int32
// Folded weights:
__device__ float g_W12[32 * 32];    // w1b @ w2a
__device__ float g_b12[32];         // b1b @ w2a
__device__ float g_w23[32];         // w2b @ w3
__device__ float g_c23;             // b2b . w3

// ---------------------------------------------------------------------------
// K0: dtype detect (int64 odd words are zero high halves) + weight folding.
// ---------------------------------------------------------------------------
__global__ void k_init(const int* __restrict__ ei_w, int nWords,
                       const float* __restrict__ w1b, const float* __restrict__ b1b,
                       const float* __restrict__ w2a, const float* __restrict__ w2b,
                       const float* __restrict__ b2b, const float* __restrict__ w3) {
    __shared__ int any_nonzero;
    int tid = threadIdx.x;
    if (tid == 0) any_nonzero = 0;
    __syncthreads();
    int nz = 0;
    for (int i = tid; i < 2048; i += blockDim.x) {
        int w = 2 * i + 1;
        if (w < nWords && ei_w[w] != 0) nz = 1;
    }
    if (nz) atomicOr(&any_nonzero, 1);
    __syncthreads();
    if (tid == 0) g_is64 = any_nonzero ? 0 : 1;

    int k = tid >> 5, o = tid & 31;
    float acc = 0.f;
#pragma unroll
    for (int j = 0; j < 32; ++j)
        acc = fmaf(w1b[k * 32 + j], w2a[j * 32 + o], acc);
    g_W12[k * 32 + o] = acc;

    if (tid < 32) {
        float b = 0.f, w = 0.f;
#pragma unroll
        for (int j = 0; j < 32; ++j) {
            b = fmaf(b1b[j], w2a[j * 32 + tid], b);
            w = fmaf(w2b[tid * 32 + j], w3[j], w);
        }
        g_b12[tid] = b;
        g_w23[tid] = w;
    }
    if (tid == 0) {
        float c = 0.f;
#pragma unroll
        for (int j = 0; j < 32; ++j) c = fmaf(b2b[j], w3[j], c);
        g_c23 = c;
    }
}

__device__ __forceinline__ void load_edge(const int* __restrict__ ei, int nE,
                                          int e, int& src, int& dst) {
    if (g_is64) {
        const long long* p = (const long long*)ei;
        src = (int)p[e];
        dst = (int)p[(size_t)nE + e];
    } else {
        src = ei[e];
        dst = ei[nE + e];
    }
}

// --------------------------- CSR build (counting sort by dst) ---------------
__global__ void k_zero(int nN) {
    int i = blockIdx.x * blockDim.x + threadIdx.x;
    if (i < nN) g_cnt[i] = 0;
}

__global__ void k_count(const int* __restrict__ ei, int nE) {
    int e = blockIdx.x * blockDim.x + threadIdx.x;
    if (e >= nE) return;
    int src, dst;
    load_edge(ei, nE, e, src, dst);
    atomicAdd(&g_cnt[dst], 1);
}

// Phase 1: per-block sums of g_cnt (SCAN_BS counts per block).
__global__ void k_bsum(int nN) {
    __shared__ int sm[SCAN_BS / 32];
    int i = blockIdx.x * SCAN_BS + threadIdx.x;
    int v = (i < nN) ? g_cnt[i] : 0;
    for (int o = 16; o > 0; o >>= 1) v += __shfl_xor_sync(0xffffffffu, v, o);
    if ((threadIdx.x & 31) == 0) sm[threadIdx.x >> 5] = v;
    __syncthreads();
    if (threadIdx.x == 0) {
        int s = 0;
        for (int w = 0; w < SCAN_BS / 32; ++w) s += sm[w];
        g_bsum[blockIdx.x] = s;
    }
}

// Phase 2: one small block computes INCLUSIVE scan of the <=NBMAX block sums.
__global__ void k_scan_tops(int nB, int nN, int nE) {
    __shared__ int sm[2][NBMAX];
    int tid = threadIdx.x;
    for (int i = tid; i < nB; i += blockDim.x) sm[0][i] = g_bsum[i];
    __syncthreads();
    int p = 0;
    for (int off = 1; off < nB; off <<= 1) {
        for (int i = tid; i < nB; i += blockDim.x)
            sm[p ^ 1][i] = sm[p][i] + ((i >= off) ? sm[p][i - off] : 0);
        __syncthreads();
        p ^= 1;
    }
    for (int i = tid; i < nB; i += blockDim.x)
        g_bsum[i] = sm[p][i];   // inclusive; phase 3 uses [blockIdx-1] as base
    if (tid == 0) g_off[nN] = nE;
}

// Phase 3: each block scans its SCAN_BS counts and writes exclusive offsets.
__global__ void k_offsets(int nN) {
    __shared__ int sm[2][SCAN_BS];
    int tid = threadIdx.x;
    int i = blockIdx.x * SCAN_BS + tid;
    int c = (i < nN) ? g_cnt[i] : 0;
    sm[0][tid] = c;
    __syncthreads();
    int p = 0;
#pragma unroll
    for (int off = 1; off < SCAN_BS; off <<= 1) {
        sm[p ^ 1][tid] = sm[p][tid] + ((tid >= off) ? sm[p][tid - off] : 0);
        __syncthreads();
        p ^= 1;
    }
    int base = (blockIdx.x > 0) ? g_bsum[blockIdx.x - 1] : 0;
    if (i < nN) {
        int excl = base + sm[p][tid] - c;
        g_off[i] = excl;
        g_cur[i] = excl;
    }
}

__global__ void k_scatter(const int* __restrict__ ei, int nE) {
    int e = blockIdx.x * blockDim.x + threadIdx.x;
    if (e >= nE) return;
    int src, dst;
    load_edge(ei, nE, e, src, dst);
    int pos = atomicAdd(&g_cur[dst], 1);
    g_ssrc[pos] = src;
}

// ---------------------------------------------------------------------------
// K1: y1 = x @ w1a  (nN x 128)@(128 x 32). 4 warps, 2 adjacent nodes per iter,
// weight slice in regs, 4-way split accumulators, one barrier per iteration.
// ---------------------------------------------------------------------------
__global__ __launch_bounds__(128, 8) void k_proj1(const float* __restrict__ x,
                        const float* __restrict__ w1a, int nN) {
    const int lane = threadIdx.x & 31;
    const int wid  = threadIdx.x >> 5;   // 0..3
    float wreg[32];
#pragma unroll
    for (int k = 0; k < 32; ++k)
        wreg[k] = w1a[(wid * 32 + k) * 32 + lane];

    __shared__ float part[2][2][4][32];  // [buf][node][warp][lane]

    int buf = 0;
    for (int base = blockIdx.x * 2; base < nN; base += gridDim.x * 2) {
        int n1 = base + 1;
        bool has1 = (n1 < nN);
        float xa = x[(size_t)base * 128 + wid * 32 + lane];
        float xb = has1 ? x[(size_t)n1 * 128 + wid * 32 + lane] : 0.f;
        float a0 = 0.f, a1 = 0.f, a2 = 0.f, a3 = 0.f;
        float c0 = 0.f, c1 = 0.f, c2 = 0.f, c3 = 0.f;
#pragma unroll
        for (int k = 0; k < 32; k += 4) {
            a0 = fmaf(__shfl_sync(0xffffffffu, xa, k + 0), wreg[k + 0], a0);
            c0 = fmaf(__shfl_sync(0xffffffffu, xb, k + 0), wreg[k + 0], c0);
            a1 = fmaf(__shfl_sync(0xffffffffu, xa, k + 1), wreg[k + 1], a1);
            c1 = fmaf(__shfl_sync(0xffffffffu, xb, k + 1), wreg[k + 1], c1);
            a2 = fmaf(__shfl_sync(0xffffffffu, xa, k + 2), wreg[k + 2], a2);
            c2 = fmaf(__shfl_sync(0xffffffffu, xb, k + 2), wreg[k + 2], c2);
            a3 = fmaf(__shfl_sync(0xffffffffu, xa, k + 3), wreg[k + 3], a3);
            c3 = fmaf(__shfl_sync(0xffffffffu, xb, k + 3), wreg[k + 3], c3);
        }
        part[buf][0][wid][lane] = (a0 + a1) + (a2 + a3);
        part[buf][1][wid][lane] = (c0 + c1) + (c2 + c3);
        __syncthreads();
        if (wid == 0) {
            g_Y1[base * 32 + lane] = part[buf][0][0][lane] + part[buf][0][1][lane]
                                   + part[buf][0][2][lane] + part[buf][0][3][lane];
        } else if (wid == 1 && has1) {
            g_Y1[n1 * 32 + lane] = part[buf][1][0][lane] + part[buf][1][1][lane]
                                 + part[buf][1][2][lane] + part[buf][1][3][lane];
        }
        buf ^= 1;
    }
}

// ---------------------------------------------------------------------------
// K2: fused aggregation + MLP1 (+ conv2 first linear, folded into W12).
// Warp per dst node: lanes = channels; register accumulation, no atomics.
// ---------------------------------------------------------------------------
__global__ __launch_bounds__(256, 4) void k_aggmlp1(const float* __restrict__ b1a, int nN) {
    const int lane = threadIdx.x & 31;
    float wc[32];
#pragma unroll
    for (int k = 0; k < 32; ++k)
        wc[k] = g_W12[k * 32 + lane];
    const float ba = b1a[lane];
    const float bb = g_b12[lane];

    int gw = (blockIdx.x * blockDim.x + threadIdx.x) >> 5;
    int nw = (gridDim.x * blockDim.x) >> 5;
    for (int dst = gw; dst < nN; dst += nw) {
        int beg = g_off[dst], end = g_off[dst + 1];
        float a0 = g_Y1[dst * 32 + lane];   // self (eps = 0)
        float a1 = 0.f, a2 = 0.f, a3 = 0.f;
        int i = beg;
        for (; i + 4 <= end; i += 4) {
            int s0 = g_ssrc[i], s1 = g_ssrc[i + 1], s2 = g_ssrc[i + 2], s3 = g_ssrc[i + 3];
            a0 += g_Y1[s0 * 32 + lane];
            a1 += g_Y1[s1 * 32 + lane];
            a2 += g_Y1[s2 * 32 + lane];
            a3 += g_Y1[s3 * 32 + lane];
        }
        for (; i < end; ++i) a0 += g_Y1[g_ssrc[i] * 32 + lane];
        float z = (a0 + a1) + (a2 + a3);
        float t = fmaxf(z + ba, 0.f);
        float y0 = bb, y1 = 0.f, y2 = 0.f, y3 = 0.f;
#pragma unroll
        for (int k = 0; k < 32; k += 4) {
            y0 = fmaf(__shfl_sync(0xffffffffu, t, k + 0), wc[k + 0], y0);
            y1 = fmaf(__shfl_sync(0xffffffffu, t, k + 1), wc[k + 1], y1);
            y2 = fmaf(__shfl_sync(0xffffffffu, t, k + 2), wc[k + 2], y2);
            y3 = fmaf(__shfl_sync(0xffffffffu, t, k + 3), wc[k + 3], y3);
        }
        g_Y2[dst * 32 + lane] = (y0 + y1) + (y2 + y3);
    }
}

// ---------------------------------------------------------------------------
// K3: fused aggregation + MLP2 (+ conv3 linear, folded into w23).
// ---------------------------------------------------------------------------
__global__ __launch_bounds__(256, 8) void k_aggs(const float* __restrict__ b2a, int nN) {
    const int lane = threadIdx.x & 31;
    const float ba = b2a[lane];
    const float wl = g_w23[lane];
    const float c23 = g_c23;

    int gw = (blockIdx.x * blockDim.x + threadIdx.x) >> 5;
    int nw = (gridDim.x * blockDim.x) >> 5;
    for (int dst = gw; dst < nN; dst += nw) {
        int beg = g_off[dst], end = g_off[dst + 1];
        float a0 = g_Y2[dst * 32 + lane];
        float a1 = 0.f, a2 = 0.f, a3 = 0.f;
        int i = beg;
        for (; i + 4 <= end; i += 4) {
            int s0 = g_ssrc[i], s1 = g_ssrc[i + 1], s2 = g_ssrc[i + 2], s3 = g_ssrc[i + 3];
            a0 += g_Y2[s0 * 32 + lane];
            a1 += g_Y2[s1 * 32 + lane];
            a2 += g_Y2[s2 * 32 + lane];
            a3 += g_Y2[s3 * 32 + lane];
        }
        for (; i < end; ++i) a0 += g_Y2[g_ssrc[i] * 32 + lane];
        float z = (a0 + a1) + (a2 + a3);
        float sp = fmaxf(z + ba, 0.f) * wl;
#pragma unroll
        for (int o = 16; o > 0; o >>= 1)
            sp += __shfl_xor_sync(0xffffffffu, sp, o);
        if (lane == 0) g_S[dst] = sp + c23;
    }
}

// ---------------------------------------------------------------------------
// K4: conv3 aggregation, thread per dst: out = S[dst] + sum S[src] + b3.
// ---------------------------------------------------------------------------
__global__ void k_out(const float* __restrict__ b3, float* __restrict__ out, int nN) {
    int dst = blockIdx.x * blockDim.x + threadIdx.x;
    if (dst >= nN) return;
    int beg = g_off[dst], end = g_off[dst + 1];
    float a0 = g_S[dst], a1 = 0.f, a2 = 0.f, a3 = 0.f;
    int i = beg;
    for (; i + 4 <= end; i += 4) {
        a0 += g_S[g_ssrc[i]];
        a1 += g_S[g_ssrc[i + 1]];
        a2 += g_S[g_ssrc[i + 2]];
        a3 += g_S[g_ssrc[i + 3]];
    }
    for (; i < end; ++i) a0 += g_S[g_ssrc[i]];
    out[dst] = (a0 + a1) + (a2 + a3) + b3[0];
}

// ---------------------------------------------------------------------------
extern "C" void kernel_launch(void* const* d_in, const int* in_sizes, int n_in,
                              void* d_out, int out_size) {
    const float* x   = (const float*)d_in[0];
    const int*   ei  = (const int*)d_in[1];
    const float* w1a = (const float*)d_in[2];
    const float* b1a = (const float*)d_in[3];
    const float* w1b = (const float*)d_in[4];
    const float* b1b = (const float*)d_in[5];
    const float* w2a = (const float*)d_in[6];
    const float* b2a = (const float*)d_in[7];
    const float* w2b = (const float*)d_in[8];
    const float* b2b = (const float*)d_in[9];
    const float* w3  = (const float*)d_in[10];
    const float* b3  = (const float*)d_in[11];

    int nN = in_sizes[0] / 128;
    int nE = in_sizes[1] / 2;
    int nB = (nN + SCAN_BS - 1) / SCAN_BS;
    float* out = (float*)d_out;

    // dtype detect + weight folding
    k_init<<<1, 1024>>>(ei, 2 * nE, w1b, b1b, w2a, w2b, b2b, w3);
    // CSR build: counting sort by destination (chip-wide 3-phase scan)
    k_zero<<<(nN + 255) / 256, 256>>>(nN);
    k_count<<<(nE + 255) / 256, 256>>>(ei, nE);
    k_bsum<<<nB, SCAN_BS>>>(nN);
    k_scan_tops<<<1, 512>>>(nB, nN, nE);
    k_offsets<<<nB, SCAN_BS>>>(nN);
    k_scatter<<<(nE + 255) / 256, 256>>>(ei, nE);
    // conv1 projection 128->32 (commutes with aggregation)
    k_proj1<<<4736, 128>>>(x, w1a, nN);
    // conv1 aggregate + MLP1 (+conv2 lin A) fused, atomic-free
    k_aggmlp1<<<2368, 256>>>(b1a, nN);
    // conv2 aggregate + MLP2 (+conv3 lin) fused -> scalar S
    k_aggs<<<2368, 256>>>(b2a, nN);
    // conv3 aggregate scalars -> out
    k_out<<<(nN + 255) / 256, 256>>>(b3, out, nN);
}

// round 15
// speedup vs baseline: 1.9021x; 1.0523x over previous
#include <cuda_runtime.h>

#define NMAX 100000
#define NEMAX 1700000
#define SCAN_BS 512
#define NBP ((NMAX + SCAN_BS - 1) / SCAN_BS)

// Scratch (__device__ globals; allocation-free rule)
__device__ __align__(16) float g_Y1[NMAX * 32];
__device__ __align__(16) float g_Y2[NMAX * 32];
__device__ float g_S[NMAX];
__device__ int   g_cnt[NMAX];
__device__ int   g_off[NMAX + 1];
__device__ int   g_cur[NMAX];
__device__ int   g_ssrc[NEMAX];
__device__ int   g_part[NBP];       // published block totals (+1), 0 = not ready
__device__ int   g_is64;            // 1 if edge_index is int64, 0 if int32
// Folded weights:
__device__ float g_W12[32 * 32];    // w1b @ w2a
__device__ float g_b12[32];         // b1b @ w2a
__device__ float g_w23[32];         // w2b @ w3
__device__ float g_c23;             // b2b . w3

// ---------------------------------------------------------------------------
// K0: block 0 = dtype detect + weight folding; ALL blocks zero g_cnt/g_part.
// ---------------------------------------------------------------------------
__global__ void k_init(const int* __restrict__ ei_w, int nWords, int nN,
                       const float* __restrict__ w1b, const float* __restrict__ b1b,
                       const float* __restrict__ w2a, const float* __restrict__ w2b,
                       const float* __restrict__ b2b, const float* __restrict__ w3) {
    int tid = threadIdx.x;
    // zeroing (grid-wide)
    for (int i = blockIdx.x * blockDim.x + tid; i < nN; i += gridDim.x * blockDim.x)
        g_cnt[i] = 0;
    for (int i = blockIdx.x * blockDim.x + tid; i < NBP; i += gridDim.x * blockDim.x)
        g_part[i] = 0;

    if (blockIdx.x != 0) return;

    __shared__ int any_nonzero;
    if (tid == 0) any_nonzero = 0;
    __syncthreads();
    int nz = 0;
    for (int i = tid; i < 2048; i += blockDim.x) {
        int w = 2 * i + 1;
        if (w < nWords && ei_w[w] != 0) nz = 1;
    }
    if (nz) atomicOr(&any_nonzero, 1);
    __syncthreads();
    if (tid == 0) g_is64 = any_nonzero ? 0 : 1;

    int k = tid >> 5, o = tid & 31;
    float acc = 0.f;
#pragma unroll
    for (int j = 0; j < 32; ++j)
        acc = fmaf(w1b[k * 32 + j], w2a[j * 32 + o], acc);
    g_W12[k * 32 + o] = acc;

    if (tid < 32) {
        float b = 0.f, w = 0.f;
#pragma unroll
        for (int j = 0; j < 32; ++j) {
            b = fmaf(b1b[j], w2a[j * 32 + tid], b);
            w = fmaf(w2b[tid * 32 + j], w3[j], w);
        }
        g_b12[tid] = b;
        g_w23[tid] = w;
    }
    if (tid == 0) {
        float c = 0.f;
#pragma unroll
        for (int j = 0; j < 32; ++j) c = fmaf(b2b[j], w3[j], c);
        g_c23 = c;
    }
}

__device__ __forceinline__ void load_edge(const int* __restrict__ ei, int nE,
                                          int e, int& src, int& dst) {
    if (g_is64) {
        const long long* p = (const long long*)ei;
        src = (int)p[e];
        dst = (int)p[(size_t)nE + e];
    } else {
        src = ei[e];
        dst = ei[nE + e];
    }
}

// ---------------------------------------------------------------------------
// K1: count in-degree per dst.
// ---------------------------------------------------------------------------
__global__ void k_count(const int* __restrict__ ei, int nE) {
    int e = blockIdx.x * blockDim.x + threadIdx.x;
    if (e >= nE) return;
    int src, dst;
    load_edge(ei, nE, e, src, dst);
    atomicAdd(&g_cnt[dst], 1);
}

// ---------------------------------------------------------------------------
// K2: single-pass exclusive scan (aggregate-only lookback).
// Each block scans its 512 counts in smem, publishes total+1, warp 0 spin-sums
// all predecessors (they are scheduled earlier; no chained dependency).
// ---------------------------------------------------------------------------
__global__ __launch_bounds__(SCAN_BS) void k_scan(int nN, int nE) {
    __shared__ int sm[2][SCAN_BS];
    __shared__ int s_base;
    int tid = threadIdx.x, bid = blockIdx.x;
    int i = bid * SCAN_BS + tid;
    int c = (i < nN) ? g_cnt[i] : 0;
    sm[0][tid] = c;
    __syncthreads();
    int p = 0;
#pragma unroll
    for (int off = 1; off < SCAN_BS; off <<= 1) {
        sm[p ^ 1][tid] = sm[p][tid] + ((tid >= off) ? sm[p][tid - off] : 0);
        __syncthreads();
        p ^= 1;
    }
    int incl = sm[p][tid];
    if (tid == SCAN_BS - 1)
        atomicExch(&g_part[bid], incl + 1);   // publish (device-coherent)

    if (tid < 32) {
        int base = 0;
        for (int j = (int)tid; j < bid; j += 32) {
            int v;
            do { v = atomicAdd(&g_part[j], 0); } while (v == 0);
            base += v - 1;
        }
#pragma unroll
        for (int o = 16; o > 0; o >>= 1)
            base += __shfl_xor_sync(0xffffffffu, base, o);
        if (tid == 0) s_base = base;
    }
    __syncthreads();
    int base = s_base;
    if (i < nN) {
        int excl = base + incl - c;
        g_off[i] = excl;
        g_cur[i] = excl;
    }
    if (bid == (int)gridDim.x - 1 && tid == SCAN_BS - 1) g_off[nN] = nE;
}

// ---------------------------------------------------------------------------
// K3: FUSED proj1 + scatter (independent work, one launch, real concurrency).
// Blocks [0, projBlocks): y1 = x @ w1a (2 nodes/iter, weight slice in regs).
// Blocks [projBlocks, ...): scatter edge e's src into CSR slot of dst.
// ---------------------------------------------------------------------------
__global__ __launch_bounds__(128, 8) void k_proj_scatter(
        const float* __restrict__ x, const float* __restrict__ w1a, int nN,
        const int* __restrict__ ei, int nE, int projBlocks) {
    __shared__ float part[2][2][4][32];  // [buf][node][warp][lane]
    const int lane = threadIdx.x & 31;

    if ((int)blockIdx.x >= projBlocks) {
        // ---- scatter role ----
        int e = (blockIdx.x - projBlocks) * 128 + threadIdx.x;
        if (e < nE) {
            int src, dst;
            load_edge(ei, nE, e, src, dst);
            int pos = atomicAdd(&g_cur[dst], 1);
            g_ssrc[pos] = src;
        }
        return;
    }

    // ---- projection role ----
    const int wid = threadIdx.x >> 5;   // 0..3
    float wreg[32];
#pragma unroll
    for (int k = 0; k < 32; ++k)
        wreg[k] = w1a[(wid * 32 + k) * 32 + lane];

    int buf = 0;
    for (int base = blockIdx.x * 2; base < nN; base += projBlocks * 2) {
        int n1 = base + 1;
        bool has1 = (n1 < nN);
        float xa = x[(size_t)base * 128 + wid * 32 + lane];
        float xb = has1 ? x[(size_t)n1 * 128 + wid * 32 + lane] : 0.f;
        float a0 = 0.f, a1 = 0.f, a2 = 0.f, a3 = 0.f;
        float c0 = 0.f, c1 = 0.f, c2 = 0.f, c3 = 0.f;
#pragma unroll
        for (int k = 0; k < 32; k += 4) {
            a0 = fmaf(__shfl_sync(0xffffffffu, xa, k + 0), wreg[k + 0], a0);
            c0 = fmaf(__shfl_sync(0xffffffffu, xb, k + 0), wreg[k + 0], c0);
            a1 = fmaf(__shfl_sync(0xffffffffu, xa, k + 1), wreg[k + 1], a1);
            c1 = fmaf(__shfl_sync(0xffffffffu, xb, k + 1), wreg[k + 1], c1);
            a2 = fmaf(__shfl_sync(0xffffffffu, xa, k + 2), wreg[k + 2], a2);
            c2 = fmaf(__shfl_sync(0xffffffffu, xb, k + 2), wreg[k + 2], c2);
            a3 = fmaf(__shfl_sync(0xffffffffu, xa, k + 3), wreg[k + 3], a3);
            c3 = fmaf(__shfl_sync(0xffffffffu, xb, k + 3), wreg[k + 3], c3);
        }
        part[buf][0][wid][lane] = (a0 + a1) + (a2 + a3);
        part[buf][1][wid][lane] = (c0 + c1) + (c2 + c3);
        __syncthreads();
        if (wid == 0) {
            g_Y1[base * 32 + lane] = part[buf][0][0][lane] + part[buf][0][1][lane]
                                   + part[buf][0][2][lane] + part[buf][0][3][lane];
        } else if (wid == 1 && has1) {
            g_Y1[n1 * 32 + lane] = part[buf][1][0][lane] + part[buf][1][1][lane]
                                 + part[buf][1][2][lane] + part[buf][1][3][lane];
        }
        buf ^= 1;
    }
}

// ---------------------------------------------------------------------------
// K4: fused aggregation + MLP1 (+ conv2 first linear, folded into W12).
// Warp per dst node: lanes = channels; register accumulation, no atomics.
// ---------------------------------------------------------------------------
__global__ __launch_bounds__(256, 4) void k_aggmlp1(const float* __restrict__ b1a, int nN) {
    const int lane = threadIdx.x & 31;
    float wc[32];
#pragma unroll
    for (int k = 0; k < 32; ++k)
        wc[k] = g_W12[k * 32 + lane];
    const float ba = b1a[lane];
    const float bb = g_b12[lane];

    int gw = (blockIdx.x * blockDim.x + threadIdx.x) >> 5;
    int nw = (gridDim.x * blockDim.x) >> 5;
    for (int dst = gw; dst < nN; dst += nw) {
        int beg = g_off[dst], end = g_off[dst + 1];
        float a0 = g_Y1[dst * 32 + lane];   // self (eps = 0)
        float a1 = 0.f, a2 = 0.f, a3 = 0.f;
        int i = beg;
        for (; i + 4 <= end; i += 4) {
            int s0 = g_ssrc[i], s1 = g_ssrc[i + 1], s2 = g_ssrc[i + 2], s3 = g_ssrc[i + 3];
            a0 += g_Y1[s0 * 32 + lane];
            a1 += g_Y1[s1 * 32 + lane];
            a2 += g_Y1[s2 * 32 + lane];
            a3 += g_Y1[s3 * 32 + lane];
        }
        for (; i < end; ++i) a0 += g_Y1[g_ssrc[i] * 32 + lane];
        float z = (a0 + a1) + (a2 + a3);
        float t = fmaxf(z + ba, 0.f);
        float y0 = bb, y1 = 0.f, y2 = 0.f, y3 = 0.f;
#pragma unroll
        for (int k = 0; k < 32; k += 4) {
            y0 = fmaf(__shfl_sync(0xffffffffu, t, k + 0), wc[k + 0], y0);
            y1 = fmaf(__shfl_sync(0xffffffffu, t, k + 1), wc[k + 1], y1);
            y2 = fmaf(__shfl_sync(0xffffffffu, t, k + 2), wc[k + 2], y2);
            y3 = fmaf(__shfl_sync(0xffffffffu, t, k + 3), wc[k + 3], y3);
        }
        g_Y2[dst * 32 + lane] = (y0 + y1) + (y2 + y3);
    }
}

// ---------------------------------------------------------------------------
// K5: fused aggregation + MLP2 (+ conv3 linear, folded into w23).
// ---------------------------------------------------------------------------
__global__ __launch_bounds__(256, 8) void k_aggs(const float* __restrict__ b2a, int nN) {
    const int lane = threadIdx.x & 31;
    const float ba = b2a[lane];
    const float wl = g_w23[lane];
    const float c23 = g_c23;

    int gw = (blockIdx.x * blockDim.x + threadIdx.x) >> 5;
    int nw = (gridDim.x * blockDim.x) >> 5;
    for (int dst = gw; dst < nN; dst += nw) {
        int beg = g_off[dst], end = g_off[dst + 1];
        float a0 = g_Y2[dst * 32 + lane];
        float a1 = 0.f, a2 = 0.f, a3 = 0.f;
        int i = beg;
        for (; i + 4 <= end; i += 4) {
            int s0 = g_ssrc[i], s1 = g_ssrc[i + 1], s2 = g_ssrc[i + 2], s3 = g_ssrc[i + 3];
            a0 += g_Y2[s0 * 32 + lane];
            a1 += g_Y2[s1 * 32 + lane];
            a2 += g_Y2[s2 * 32 + lane];
            a3 += g_Y2[s3 * 32 + lane];
        }
        for (; i < end; ++i) a0 += g_Y2[g_ssrc[i] * 32 + lane];
        float z = (a0 + a1) + (a2 + a3);
        float sp = fmaxf(z + ba, 0.f) * wl;
#pragma unroll
        for (int o = 16; o > 0; o >>= 1)
            sp += __shfl_xor_sync(0xffffffffu, sp, o);
        if (lane == 0) g_S[dst] = sp + c23;
    }
}

// ---------------------------------------------------------------------------
// K6: conv3 aggregation, thread per dst: out = S[dst] + sum S[src] + b3.
// ---------------------------------------------------------------------------
__global__ void k_out(const float* __restrict__ b3, float* __restrict__ out, int nN) {
    int dst = blockIdx.x * blockDim.x + threadIdx.x;
    if (dst >= nN) return;
    int beg = g_off[dst], end = g_off[dst + 1];
    float a0 = g_S[dst], a1 = 0.f, a2 = 0.f, a3 = 0.f;
    int i = beg;
    for (; i + 4 <= end; i += 4) {
        a0 += g_S[g_ssrc[i]];
        a1 += g_S[g_ssrc[i + 1]];
        a2 += g_S[g_ssrc[i + 2]];
        a3 += g_S[g_ssrc[i + 3]];
    }
    for (; i < end; ++i) a0 += g_S[g_ssrc[i]];
    out[dst] = (a0 + a1) + (a2 + a3) + b3[0];
}

// ---------------------------------------------------------------------------
extern "C" void kernel_launch(void* const* d_in, const int* in_sizes, int n_in,
                              void* d_out, int out_size) {
    const float* x   = (const float*)d_in[0];
    const int*   ei  = (const int*)d_in[1];
    const float* w1a = (const float*)d_in[2];
    const float* b1a = (const float*)d_in[3];
    const float* w1b = (const float*)d_in[4];
    const float* b1b = (const float*)d_in[5];
    const float* w2a = (const float*)d_in[6];
    const float* b2a = (const float*)d_in[7];
    const float* w2b = (const float*)d_in[8];
    const float* b2b = (const float*)d_in[9];
    const float* w3  = (const float*)d_in[10];
    const float* b3  = (const float*)d_in[11];

    int nN = in_sizes[0] / 128;
    int nE = in_sizes[1] / 2;
    int nB = (nN + SCAN_BS - 1) / SCAN_BS;
    int projBlocks = 4736;
    int scatBlocks = (nE + 127) / 128;
    float* out = (float*)d_out;

    // dtype detect + weight folding + zero cnt/part   (1 launch)
    k_init<<<98, 1024>>>(ei, 2 * nE, nN, w1b, b1b, w2a, w2b, b2b, w3);
    // CSR: count degrees                               (1 launch)
    k_count<<<(nE + 255) / 256, 256>>>(ei, nE);
    // CSR: single-pass scan with aggregate lookback    (1 launch)
    k_scan<<<nB, SCAN_BS>>>(nN, nE);
    // conv1 projection 128->32 CONCURRENT with CSR scatter (1 launch)
    k_proj_scatter<<<projBlocks + scatBlocks, 128>>>(x, w1a, nN, ei, nE, projBlocks);
    // conv1 aggregate + MLP1 (+conv2 lin A) fused, atomic-free
    k_aggmlp1<<<2368, 256>>>(b1a, nN);
    // conv2 aggregate + MLP2 (+conv3 lin) fused -> scalar S
    k_aggs<<<2368, 256>>>(b2a, nN);
    // conv3 aggregate scalars -> out
    k_out<<<(nN + 255) / 256, 256>>>(b3, out, nN);
}

// round 17
// speedup vs baseline: 2.1467x; 1.1286x over previous
#include <cuda_runtime.h>

#define NMAX 100000
#define NEMAX 1700000
#define SCAN_BS 512
#define NBP ((NMAX + SCAN_BS - 1) / SCAN_BS)

// Scratch (__device__ globals; allocation-free rule)
__device__ __align__(16) float g_Y1[NMAX * 32];
__device__ __align__(16) float g_Y2[NMAX * 32];
__device__ float g_S[NMAX];
__device__ int   g_cnt[NMAX];
__device__ int   g_off[NMAX + 1];
__device__ int   g_cur[NMAX];
__device__ int   g_ssrc[NEMAX];
__device__ int   g_part[NBP];       // published block totals (+1), 0 = not ready
__device__ int   g_is64;            // 1 if edge_index is int64, 0 if int32
// Folded weights:
__device__ float g_W12[32 * 32];    // w1b @ w2a
__device__ float g_b12[32];         // b1b @ w2a
__device__ float g_w23[32];         // w2b @ w3
__device__ float g_c23;             // b2b . w3

// ---------------------------------------------------------------------------
// K0: block 0 = dtype detect + weight folding; ALL blocks zero g_cnt/g_part.
// ---------------------------------------------------------------------------
__global__ void k_init(const int* __restrict__ ei_w, int nWords, int nN,
                       const float* __restrict__ w1b, const float* __restrict__ b1b,
                       const float* __restrict__ w2a, const float* __restrict__ w2b,
                       const float* __restrict__ b2b, const float* __restrict__ w3) {
    int tid = threadIdx.x;
    for (int i = blockIdx.x * blockDim.x + tid; i < nN; i += gridDim.x * blockDim.x)
        g_cnt[i] = 0;
    for (int i = blockIdx.x * blockDim.x + tid; i < NBP; i += gridDim.x * blockDim.x)
        g_part[i] = 0;

    if (blockIdx.x != 0) return;

    __shared__ int any_nonzero;
    if (tid == 0) any_nonzero = 0;
    __syncthreads();
    int nz = 0;
    for (int i = tid; i < 2048; i += blockDim.x) {
        int w = 2 * i + 1;
        if (w < nWords && ei_w[w] != 0) nz = 1;
    }
    if (nz) atomicOr(&any_nonzero, 1);
    __syncthreads();
    if (tid == 0) g_is64 = any_nonzero ? 0 : 1;

    int k = tid >> 5, o = tid & 31;
    float acc = 0.f;
#pragma unroll
    for (int j = 0; j < 32; ++j)
        acc = fmaf(w1b[k * 32 + j], w2a[j * 32 + o], acc);
    g_W12[k * 32 + o] = acc;

    if (tid < 32) {
        float b = 0.f, w = 0.f;
#pragma unroll
        for (int j = 0; j < 32; ++j) {
            b = fmaf(b1b[j], w2a[j * 32 + tid], b);
            w = fmaf(w2b[tid * 32 + j], w3[j], w);
        }
        g_b12[tid] = b;
        g_w23[tid] = w;
    }
    if (tid == 0) {
        float c = 0.f;
#pragma unroll
        for (int j = 0; j < 32; ++j) c = fmaf(b2b[j], w3[j], c);
        g_c23 = c;
    }
}

__device__ __forceinline__ void load_edge(const int* __restrict__ ei, int nE,
                                          int e, int& src, int& dst) {
    if (g_is64) {
        const long long* p = (const long long*)ei;
        src = (int)p[e];
        dst = (int)p[(size_t)nE + e];
    } else {
        src = ei[e];
        dst = ei[nE + e];
    }
}

// ---------------------------------------------------------------------------
// K1: count in-degree per dst.
// ---------------------------------------------------------------------------
__global__ void k_count(const int* __restrict__ ei, int nE) {
    int e = blockIdx.x * blockDim.x + threadIdx.x;
    if (e >= nE) return;
    int src, dst;
    load_edge(ei, nE, e, src, dst);
    atomicAdd(&g_cnt[dst], 1);
}

// ---------------------------------------------------------------------------
// K2: single-pass exclusive scan (aggregate-only lookback).
// ---------------------------------------------------------------------------
__global__ __launch_bounds__(SCAN_BS) void k_scan(int nN, int nE) {
    __shared__ int sm[2][SCAN_BS];
    __shared__ int s_base;
    int tid = threadIdx.x, bid = blockIdx.x;
    int i = bid * SCAN_BS + tid;
    int c = (i < nN) ? g_cnt[i] : 0;
    sm[0][tid] = c;
    __syncthreads();
    int p = 0;
#pragma unroll
    for (int off = 1; off < SCAN_BS; off <<= 1) {
        sm[p ^ 1][tid] = sm[p][tid] + ((tid >= off) ? sm[p][tid - off] : 0);
        __syncthreads();
        p ^= 1;
    }
    int incl = sm[p][tid];
    if (tid == SCAN_BS - 1)
        atomicExch(&g_part[bid], incl + 1);   // publish (device-coherent)

    if (tid < 32) {
        int base = 0;
        for (int j = (int)tid; j < bid; j += 32) {
            int v;
            do { v = atomicAdd(&g_part[j], 0); } while (v == 0);
            base += v - 1;
        }
#pragma unroll
        for (int o = 16; o > 0; o >>= 1)
            base += __shfl_xor_sync(0xffffffffu, base, o);
        if (tid == 0) s_base = base;
    }
    __syncthreads();
    int base = s_base;
    if (i < nN) {
        int excl = base + incl - c;
        g_off[i] = excl;
        g_cur[i] = excl;
    }
    if (bid == (int)gridDim.x - 1 && tid == SCAN_BS - 1) g_off[nN] = nE;
}

// ---------------------------------------------------------------------------
// K3: FUSED register-tiled GEMM projection + CSR scatter.
// Proj blocks [0, projBlocks): 256-node x 32-output tile per block.
//   Thread = (tx 0..7 -> 4 outputs, ty 0..31 -> 8 nodes): 32 accumulators.
//   Per k: 1 LDS.128 (w) + 2 LDS.128 (x) + 32 FMA  -- no shuffles.
//   smem: w_s 16KB + x_s (k-major, 32x256) 32KB = 48KB -> 4 blocks/SM.
// Scatter blocks [projBlocks, +592): grid-stride edge scatter into CSR.
// ---------------------------------------------------------------------------
__global__ __launch_bounds__(256) void k_proj_scatter(
        const float* __restrict__ x, const float* __restrict__ w1a, int nN,
        const int* __restrict__ ei, int nE, int projBlocks) {
    const int tid = threadIdx.x;

    if ((int)blockIdx.x >= projBlocks) {
        // ---- scatter role (grid-stride) ----
        int sb = blockIdx.x - projBlocks;
        int nSB = gridDim.x - projBlocks;
        for (int e = sb * 256 + tid; e < nE; e += nSB * 256) {
            int src, dst;
            load_edge(ei, nE, e, src, dst);
            int pos = atomicAdd(&g_cur[dst], 1);
            g_ssrc[pos] = src;
        }
        return;
    }

    // ---- projection role ----
    __shared__ float w_s[128 * 32];      // [k][o], 16KB
    __shared__ float x_s[32][256];       // [k-chunk][node], 32KB

    const int tx = tid & 7;              // output group: o = tx*4 .. tx*4+3
    const int ty = tid >> 3;             // node group:   n = nbase + ty*8 .. +7
    const int nbase = blockIdx.x * 256;

    // stage full weight matrix (coalesced float4)
    {
        const float4* wg = (const float4*)w1a;
        float4* ws4 = (float4*)w_s;
        for (int i = tid; i < 1024; i += 256) ws4[i] = wg[i];
    }

    float acc[8][4];
#pragma unroll
    for (int i = 0; i < 8; ++i)
#pragma unroll
        for (int j = 0; j < 4; ++j) acc[i][j] = 0.f;

    for (int kc = 0; kc < 128; kc += 32) {
        __syncthreads();   // previous chunk consumed (also orders w_s on first pass)
        int node = nbase + tid;
        if (node < nN) {
            const float4* src4 = (const float4*)(x + (size_t)node * 128 + kc);
#pragma unroll
            for (int i = 0; i < 8; ++i) {
                float4 v = src4[i];
                x_s[i * 4 + 0][tid] = v.x;
                x_s[i * 4 + 1][tid] = v.y;
                x_s[i * 4 + 2][tid] = v.z;
                x_s[i * 4 + 3][tid] = v.w;
            }
        } else {
#pragma unroll
            for (int k2 = 0; k2 < 32; ++k2) x_s[k2][tid] = 0.f;
        }
        __syncthreads();

#pragma unroll
        for (int kk = 0; kk < 32; ++kk) {
            float4 wv = *(const float4*)&w_s[(kc + kk) * 32 + tx * 4];
            float4 xa = *(const float4*)&x_s[kk][ty * 8];
            float4 xb = *(const float4*)&x_s[kk][ty * 8 + 4];
            float xv[8] = {xa.x, xa.y, xa.z, xa.w, xb.x, xb.y, xb.z, xb.w};
            float wj[4] = {wv.x, wv.y, wv.z, wv.w};
#pragma unroll
            for (int i = 0; i < 8; ++i)
#pragma unroll
                for (int j = 0; j < 4; ++j)
                    acc[i][j] = fmaf(xv[i], wj[j], acc[i][j]);
        }
    }

    // epilogue: write 8 nodes x 4 outputs per thread
#pragma unroll
    for (int i = 0; i < 8; ++i) {
        int node = nbase + ty * 8 + i;
        if (node < nN) {
            float4 v = make_float4(acc[i][0], acc[i][1], acc[i][2], acc[i][3]);
            *(float4*)&g_Y1[node * 32 + tx * 4] = v;
        }
    }
}

// ---------------------------------------------------------------------------
// K4: fused aggregation + MLP1 (+ conv2 first linear, folded into W12).
// ---------------------------------------------------------------------------
__global__ __launch_bounds__(256, 4) void k_aggmlp1(const float* __restrict__ b1a, int nN) {
    const int lane = threadIdx.x & 31;
    float wc[32];
#pragma unroll
    for (int k = 0; k < 32; ++k)
        wc[k] = g_W12[k * 32 + lane];
    const float ba = b1a[lane];
    const float bb = g_b12[lane];

    int gw = (blockIdx.x * blockDim.x + threadIdx.x) >> 5;
    int nw = (gridDim.x * blockDim.x) >> 5;
    for (int dst = gw; dst < nN; dst += nw) {
        int beg = g_off[dst], end = g_off[dst + 1];
        float a0 = g_Y1[dst * 32 + lane];   // self (eps = 0)
        float a1 = 0.f, a2 = 0.f, a3 = 0.f;
        int i = beg;
        for (; i + 4 <= end; i += 4) {
            int s0 = g_ssrc[i], s1 = g_ssrc[i + 1], s2 = g_ssrc[i + 2], s3 = g_ssrc[i + 3];
            a0 += g_Y1[s0 * 32 + lane];
            a1 += g_Y1[s1 * 32 + lane];
            a2 += g_Y1[s2 * 32 + lane];
            a3 += g_Y1[s3 * 32 + lane];
        }
        for (; i < end; ++i) a0 += g_Y1[g_ssrc[i] * 32 + lane];
        float z = (a0 + a1) + (a2 + a3);
        float t = fmaxf(z + ba, 0.f);
        float y0 = bb, y1 = 0.f, y2 = 0.f, y3 = 0.f;
#pragma unroll
        for (int k = 0; k < 32; k += 4) {
            y0 = fmaf(__shfl_sync(0xffffffffu, t, k + 0), wc[k + 0], y0);
            y1 = fmaf(__shfl_sync(0xffffffffu, t, k + 1), wc[k + 1], y1);
            y2 = fmaf(__shfl_sync(0xffffffffu, t, k + 2), wc[k + 2], y2);
            y3 = fmaf(__shfl_sync(0xffffffffu, t, k + 3), wc[k + 3], y3);
        }
        g_Y2[dst * 32 + lane] = (y0 + y1) + (y2 + y3);
    }
}

// ---------------------------------------------------------------------------
// K5: fused aggregation + MLP2 (+ conv3 linear, folded into w23).
// ---------------------------------------------------------------------------
__global__ __launch_bounds__(256, 8) void k_aggs(const float* __restrict__ b2a, int nN) {
    const int lane = threadIdx.x & 31;
    const float ba = b2a[lane];
    const float wl = g_w23[lane];
    const float c23 = g_c23;

    int gw = (blockIdx.x * blockDim.x + threadIdx.x) >> 5;
    int nw = (gridDim.x * blockDim.x) >> 5;
    for (int dst = gw; dst < nN; dst += nw) {
        int beg = g_off[dst], end = g_off[dst + 1];
        float a0 = g_Y2[dst * 32 + lane];
        float a1 = 0.f, a2 = 0.f, a3 = 0.f;
        int i = beg;
        for (; i + 4 <= end; i += 4) {
            int s0 = g_ssrc[i], s1 = g_ssrc[i + 1], s2 = g_ssrc[i + 2], s3 = g_ssrc[i + 3];
            a0 += g_Y2[s0 * 32 + lane];
            a1 += g_Y2[s1 * 32 + lane];
            a2 += g_Y2[s2 * 32 + lane];
            a3 += g_Y2[s3 * 32 + lane];
        }
        for (; i < end; ++i) a0 += g_Y2[g_ssrc[i] * 32 + lane];
        float z = (a0 + a1) + (a2 + a3);
        float sp = fmaxf(z + ba, 0.f) * wl;
#pragma unroll
        for (int o = 16; o > 0; o >>= 1)
            sp += __shfl_xor_sync(0xffffffffu, sp, o);
        if (lane == 0) g_S[dst] = sp + c23;
    }
}

// ---------------------------------------------------------------------------
// K6: conv3 aggregation, thread per dst: out = S[dst] + sum S[src] + b3.
// ---------------------------------------------------------------------------
__global__ void k_out(const float* __restrict__ b3, float* __restrict__ out, int nN) {
    int dst = blockIdx.x * blockDim.x + threadIdx.x;
    if (dst >= nN) return;
    int beg = g_off[dst], end = g_off[dst + 1];
    float a0 = g_S[dst], a1 = 0.f, a2 = 0.f, a3 = 0.f;
    int i = beg;
    for (; i + 4 <= end; i += 4) {
        a0 += g_S[g_ssrc[i]];
        a1 += g_S[g_ssrc[i + 1]];
        a2 += g_S[g_ssrc[i + 2]];
        a3 += g_S[g_ssrc[i + 3]];
    }
    for (; i < end; ++i) a0 += g_S[g_ssrc[i]];
    out[dst] = (a0 + a1) + (a2 + a3) + b3[0];
}

// ---------------------------------------------------------------------------
extern "C" void kernel_launch(void* const* d_in, const int* in_sizes, int n_in,
                              void* d_out, int out_size) {
    const float* x   = (const float*)d_in[0];
    const int*   ei  = (const int*)d_in[1];
    const float* w1a = (const float*)d_in[2];
    const float* b1a = (const float*)d_in[3];
    const float* w1b = (const float*)d_in[4];
    const float* b1b = (const float*)d_in[5];
    const float* w2a = (const float*)d_in[6];
    const float* b2a = (const float*)d_in[7];
    const float* w2b = (const float*)d_in[8];
    const float* b2b = (const float*)d_in[9];
    const float* w3  = (const float*)d_in[10];
    const float* b3  = (const float*)d_in[11];

    int nN = in_sizes[0] / 128;
    int nE = in_sizes[1] / 2;
    int nB = (nN + SCAN_BS - 1) / SCAN_BS;
    int projBlocks = (nN + 255) / 256;   // 391
    int scatBlocks = 592;
    float* out = (float*)d_out;

    // dtype detect + weight folding + zero cnt/part   (1 launch)
    k_init<<<98, 1024>>>(ei, 2 * nE, nN, w1b, b1b, w2a, w2b, b2b, w3);
    // CSR: count degrees                               (1 launch)
    k_count<<<(nE + 255) / 256, 256>>>(ei, nE);
    // CSR: single-pass scan with aggregate lookback    (1 launch)
    k_scan<<<nB, SCAN_BS>>>(nN, nE);
    // conv1 projection (register-tiled GEMM) CONCURRENT with CSR scatter
    k_proj_scatter<<<projBlocks + scatBlocks, 256>>>(x, w1a, nN, ei, nE, projBlocks);
    // conv1 aggregate + MLP1 (+conv2 lin A) fused, atomic-free
    k_aggmlp1<<<2368, 256>>>(b1a, nN);
    // conv2 aggregate + MLP2 (+conv3 lin) fused -> scalar S
    k_aggs<<<2368, 256>>>(b2a, nN);
    // conv3 aggregate scalars -> out
    k_out<<<(nN + 255) / 256, 256>>>(b3, out, nN);
}